// round 1
// baseline (speedup 1.0000x reference)
#include <cuda_runtime.h>
#include <math.h>

// Problem constants (fixed by the dataset)
#define B    4
#define N    16384
#define C    256
#define C3   768
#define T    64        // categories
#define HDS  8
#define D    32        // head dim
#define GS   128       // group size
#define NG   128       // groups per batch
#define CHUNK 128
#define NCH   128      // N / CHUNK

// ---------------- scratch (static device allocations only) ----------------
__device__ int   g_tkid[B * N];
__device__ int   g_counts[B * T * NCH];     // [b][key][chunk], scanned in place
__device__ int   g_sortidx[B * N];          // sorted position -> original token
__device__ float g_y[(size_t)B * N * C];    // attention output in ORIGINAL token order

// ---------------- K1: per-token argmax + per-chunk histogram ----------------
__global__ void k_argmax_count(const float* __restrict__ sim) {
    int b = blockIdx.y, ch = blockIdx.x, tid = threadIdx.x;
    __shared__ float ss[CHUNK * T];   // 32 KB
    __shared__ int   hist[T];

    const float4* src = (const float4*)(sim + ((size_t)(b * N + ch * CHUNK)) * T);
    float4* dst = (float4*)ss;
#pragma unroll
    for (int i = tid; i < CHUNK * T / 4; i += CHUNK) dst[i] = src[i];
    if (tid < T) hist[tid] = 0;
    __syncthreads();

    const float* row = ss + tid * T;
    float best = row[0];
    int   bi   = 0;
#pragma unroll
    for (int j = 1; j < T; j++) {
        float v = row[j];
        if (v > best) { best = v; bi = j; }   // first-max == jnp.argmax tie rule
    }
    g_tkid[b * N + ch * CHUNK + tid] = bi;
    atomicAdd(&hist[bi], 1);
    __syncthreads();
    if (tid < T) g_counts[(b * T + tid) * NCH + ch] = hist[tid];
}

// ---------------- K2: per-batch exclusive scan of counts (8192 ints) ----------------
__global__ void k_scan() {
    const int PER = (T * NCH) / 1024;   // 8
    int b = blockIdx.x, tid = threadIdx.x;
    __shared__ int t1[1024], t2[1024];
    int* cnt = g_counts + b * T * NCH;

    int v[PER];
    int s = 0;
#pragma unroll
    for (int i = 0; i < PER; i++) { v[i] = cnt[tid * PER + i]; s += v[i]; }
    t1[tid] = s;
    __syncthreads();

    int* a  = t1;
    int* bb = t2;
    for (int off = 1; off < 1024; off <<= 1) {
        int x = a[tid];
        if (tid >= off) x += a[tid - off];
        bb[tid] = x;
        __syncthreads();
        int* tmp = a; a = bb; bb = tmp;
    }
    int pre = (tid == 0) ? 0 : a[tid - 1];
#pragma unroll
    for (int i = 0; i < PER; i++) { cnt[tid * PER + i] = pre; pre += v[i]; }
}

// ---------------- K3: stable scatter (counting-sort placement) ----------------
__global__ void k_scatter() {
    int b = blockIdx.y, ch = blockIdx.x, tid = threadIdx.x;
    __shared__ int keys[CHUNK];
    int token = ch * CHUNK + tid;
    int key   = g_tkid[b * N + token];
    keys[tid] = key;
    __syncthreads();
    int rank = 0;
    for (int j = 0; j < tid; j++) rank += (keys[j] == key);
    int pos = g_counts[(b * T + key) * NCH + ch] + rank;
    g_sortidx[b * N + pos] = token;
}

// ---------------- K4: grouped attention ----------------
// One block per (head, group, batch). 128 threads = one query row each.
// Dynamic smem: k[128][32] + v[128][32] + S[128][129] + toks[128]
#define SMEM_ATTN ((2 * GS * D + GS * (GS + 1)) * 4 + GS * 4)

__global__ void k_attn(const float* __restrict__ qkv,
                       const float* __restrict__ logit_scale) {
    extern __shared__ float sm[];
    float* ks = sm;
    float* vs = sm + GS * D;
    float* s  = sm + 2 * GS * D;             // also staging area for q
    int*   toks = (int*)(sm + 2 * GS * D + GS * (GS + 1));

    int head = blockIdx.x, g = blockIdx.y, b = blockIdx.z;
    int tid = threadIdx.x;

    toks[tid] = g_sortidx[b * N + g * GS + tid];
    __syncthreads();

    // cooperative gather: q -> s (staging), k -> ks, v -> vs
    for (int idx = tid; idx < GS * (D / 4); idx += GS) {
        int i = idx >> 3, p = idx & 7;
        const float4* base =
            (const float4*)(qkv + ((size_t)(b * N) + toks[i]) * C3 + head * D);
        ((float4*)s)[idx]  = base[p];              // q
        ((float4*)ks)[idx] = base[C / 4 + p];      // k (+256 floats)
        ((float4*)vs)[idx] = base[2 * (C / 4) + p];// v (+512 floats)
    }
    __syncthreads();

    float4 qr[8];
#pragma unroll
    for (int p = 0; p < 8; p++) qr[p] = ((float4*)s)[tid * 8 + p];
    __syncthreads();   // s about to be overwritten with logits

    float ls    = logit_scale[0];
    float scale = __expf(fminf(ls, 4.6051701859880914f));   // log(100)

    float* srow = s + tid * (GS + 1);   // stride 129 -> conflict-free scalar access
    float  mx = -INFINITY;
    for (int j = 0; j < GS; j++) {
        float dx = 0.f, dy = 0.f, dz = 0.f, dw = 0.f;
#pragma unroll
        for (int p = 0; p < 8; p++) {
            float4 k4 = ((float4*)ks)[j * 8 + p];   // smem broadcast
            dx += qr[p].x * k4.x;
            dy += qr[p].y * k4.y;
            dz += qr[p].z * k4.z;
            dw += qr[p].w * k4.w;
        }
        float dot = ((dx + dy) + (dz + dw)) * scale;
        srow[j] = dot;
        mx = fmaxf(mx, dot);
    }

    float sum = 0.f;
    for (int j = 0; j < GS; j++) {
        float e = __expf(srow[j] - mx);
        srow[j] = e;
        sum += e;
    }
    float rinv = 1.0f / sum;

    float4 acc[8];
#pragma unroll
    for (int p = 0; p < 8; p++) acc[p] = make_float4(0.f, 0.f, 0.f, 0.f);

    for (int j = 0; j < GS; j++) {
        float pj = srow[j];
#pragma unroll
        for (int p = 0; p < 8; p++) {
            float4 v4 = ((float4*)vs)[j * 8 + p];   // smem broadcast
            acc[p].x += pj * v4.x;
            acc[p].y += pj * v4.y;
            acc[p].z += pj * v4.z;
            acc[p].w += pj * v4.w;
        }
    }

    // scatter straight back to ORIGINAL token order (fuses inverse permutation)
    float4* outp = (float4*)(g_y + ((size_t)(b * N) + toks[tid]) * C + head * D);
#pragma unroll
    for (int p = 0; p < 8; p++) {
        acc[p].x *= rinv; acc[p].y *= rinv; acc[p].z *= rinv; acc[p].w *= rinv;
        outp[p] = acc[p];
    }
}

// ---------------- K5: projection GEMM  out = y @ W^T + b ----------------
// M = B*N = 65536, N = 256, K = 256. 64x64x16 tiles, 256 threads, 4x4 per thread.
#define BM 64
#define BN 64
#define BK 16
#define PAD 4

__global__ void k_proj(const float* __restrict__ W,
                       const float* __restrict__ bias,
                       float* __restrict__ out) {
    __shared__ float As[BK][BM + PAD];
    __shared__ float Bs[BK][BN + PAD];

    int tid = threadIdx.x;          // 256
    int tx = tid & 15, ty = tid >> 4;
    int m0 = blockIdx.y * BM;
    int n0 = blockIdx.x * BN;

    int lr  = tid >> 2;             // 0..63  (row within tile)
    int lc4 = tid & 3;              // 0..3   (float4 within 16-wide K slab)

    const float* A = g_y;
    float acc[4][4] = {};

    for (int k0 = 0; k0 < C; k0 += BK) {
        float4 a4 = *(const float4*)(A + (size_t)(m0 + lr) * C + k0 + lc4 * 4);
        float4 b4 = *(const float4*)(W + (size_t)(n0 + lr) * C + k0 + lc4 * 4);
        As[lc4 * 4 + 0][lr] = a4.x; As[lc4 * 4 + 1][lr] = a4.y;
        As[lc4 * 4 + 2][lr] = a4.z; As[lc4 * 4 + 3][lr] = a4.w;
        Bs[lc4 * 4 + 0][lr] = b4.x; Bs[lc4 * 4 + 1][lr] = b4.y;
        Bs[lc4 * 4 + 2][lr] = b4.z; Bs[lc4 * 4 + 3][lr] = b4.w;
        __syncthreads();

#pragma unroll
        for (int k = 0; k < BK; k++) {
            float4 av = *(const float4*)&As[k][ty * 4];
            float4 bv = *(const float4*)&Bs[k][tx * 4];
            acc[0][0] += av.x * bv.x; acc[0][1] += av.x * bv.y;
            acc[0][2] += av.x * bv.z; acc[0][3] += av.x * bv.w;
            acc[1][0] += av.y * bv.x; acc[1][1] += av.y * bv.y;
            acc[1][2] += av.y * bv.z; acc[1][3] += av.y * bv.w;
            acc[2][0] += av.z * bv.x; acc[2][1] += av.z * bv.y;
            acc[2][2] += av.z * bv.z; acc[2][3] += av.z * bv.w;
            acc[3][0] += av.w * bv.x; acc[3][1] += av.w * bv.y;
            acc[3][2] += av.w * bv.z; acc[3][3] += av.w * bv.w;
        }
        __syncthreads();
    }

    float4 bv = *(const float4*)(bias + n0 + tx * 4);
#pragma unroll
    for (int i = 0; i < 4; i++) {
        float4 o;
        o.x = acc[i][0] + bv.x;
        o.y = acc[i][1] + bv.y;
        o.z = acc[i][2] + bv.z;
        o.w = acc[i][3] + bv.w;
        *(float4*)(out + (size_t)(m0 + ty * 4 + i) * C + n0 + tx * 4) = o;
    }
}

// ---------------- launch ----------------
extern "C" void kernel_launch(void* const* d_in, const int* in_sizes, int n_in,
                              void* d_out, int out_size) {
    const float* qkv  = (const float*)d_in[0];
    const float* sim  = (const float*)d_in[1];
    const float* W    = (const float*)d_in[2];
    const float* bias = (const float*)d_in[3];
    const float* ls   = (const float*)d_in[4];
    float* out = (float*)d_out;

    cudaFuncSetAttribute(k_attn, cudaFuncAttributeMaxDynamicSharedMemorySize,
                         SMEM_ATTN);

    k_argmax_count<<<dim3(NCH, B), CHUNK>>>(sim);
    k_scan<<<B, 1024>>>();
    k_scatter<<<dim3(NCH, B), CHUNK>>>();
    k_attn<<<dim3(HDS, NG, B), GS, SMEM_ATTN>>>(qkv, ls);
    k_proj<<<dim3(C / BN, (B * N) / BM), 256>>>(W, bias, out);
}

// round 2
// speedup vs baseline: 1.1569x; 1.1569x over previous
#include <cuda_runtime.h>
#include <math.h>

// Problem constants (fixed by the dataset)
#define B    4
#define N    16384
#define C    256
#define C3   768
#define T    64        // categories
#define HDS  8
#define D    32        // head dim
#define GS   128       // group size
#define NG   128       // groups per batch
#define CHUNK 128
#define NCH   128      // N / CHUNK
#define JT   8         // key tile for online softmax

// ---------------- scratch (static device allocations only) ----------------
__device__ int   g_tkid[B * N];
__device__ int   g_counts[B * T * NCH];     // [b][key][chunk], scanned in place
__device__ int   g_sortidx[B * N];          // sorted position -> original token
__device__ float g_y[(size_t)B * N * C];    // attention output in ORIGINAL token order

// ---------------- K1: per-token argmax + per-chunk histogram ----------------
__global__ void k_argmax_count(const float* __restrict__ sim) {
    int b = blockIdx.y, ch = blockIdx.x, tid = threadIdx.x;
    __shared__ float ss[CHUNK * T];   // 32 KB
    __shared__ int   hist[T];

    const float4* src = (const float4*)(sim + ((size_t)(b * N + ch * CHUNK)) * T);
    float4* dst = (float4*)ss;
#pragma unroll
    for (int i = tid; i < CHUNK * T / 4; i += CHUNK) dst[i] = src[i];
    if (tid < T) hist[tid] = 0;
    __syncthreads();

    const float* row = ss + tid * T;
    float best = row[0];
    int   bi   = 0;
#pragma unroll
    for (int j = 1; j < T; j++) {
        float v = row[j];
        if (v > best) { best = v; bi = j; }   // first-max == jnp.argmax tie rule
    }
    g_tkid[b * N + ch * CHUNK + tid] = bi;
    atomicAdd(&hist[bi], 1);
    __syncthreads();
    if (tid < T) g_counts[(b * T + tid) * NCH + ch] = hist[tid];
}

// ---------------- K2: per-batch exclusive scan of counts (8192 ints) ----------------
__global__ void k_scan() {
    const int PER = (T * NCH) / 1024;   // 8
    int b = blockIdx.x, tid = threadIdx.x;
    __shared__ int t1[1024], t2[1024];
    int* cnt = g_counts + b * T * NCH;

    int v[PER];
    int s = 0;
#pragma unroll
    for (int i = 0; i < PER; i++) { v[i] = cnt[tid * PER + i]; s += v[i]; }
    t1[tid] = s;
    __syncthreads();

    int* a  = t1;
    int* bb = t2;
    for (int off = 1; off < 1024; off <<= 1) {
        int x = a[tid];
        if (tid >= off) x += a[tid - off];
        bb[tid] = x;
        __syncthreads();
        int* tmp = a; a = bb; bb = tmp;
    }
    int pre = (tid == 0) ? 0 : a[tid - 1];
#pragma unroll
    for (int i = 0; i < PER; i++) { cnt[tid * PER + i] = pre; pre += v[i]; }
}

// ---------------- K3: stable scatter (counting-sort placement) ----------------
__global__ void k_scatter() {
    int b = blockIdx.y, ch = blockIdx.x, tid = threadIdx.x;
    __shared__ int keys[CHUNK];
    int token = ch * CHUNK + tid;
    int key   = g_tkid[b * N + token];
    keys[tid] = key;
    __syncthreads();
    int rank = 0;
    for (int j = 0; j < tid; j++) rank += (keys[j] == key);
    int pos = g_counts[(b * T + key) * NCH + ch] + rank;
    g_sortidx[b * N + pos] = token;
}

// ---------------- K4: grouped attention (flash-style, no score buffer) ----------
// One block per (head, group, batch). 128 threads = one query row each.
// smem: k[128][32] + v[128][32] + toks[128] = 32.5 KB -> 5 blocks/SM.
__global__ void __launch_bounds__(128, 5)
k_attn(const float* __restrict__ qkv, const float* __restrict__ logit_scale) {
    __shared__ float ks[GS * D];
    __shared__ float vs[GS * D];
    __shared__ int   toks[GS];

    int head = blockIdx.x, g = blockIdx.y, b = blockIdx.z;
    int tid = threadIdx.x;

    toks[tid] = g_sortidx[b * N + g * GS + tid];
    __syncthreads();

    // q straight to registers (own row, 128B aligned contiguous)
    const float4* qb =
        (const float4*)(qkv + ((size_t)(b * N) + toks[tid]) * C3 + head * D);
    float4 qr[8];
#pragma unroll
    for (int p = 0; p < 8; p++) qr[p] = qb[p];

    // cooperative gather of k and v into smem
    for (int idx = tid; idx < GS * (D / 4); idx += GS) {
        int i = idx >> 3, p = idx & 7;
        const float4* base =
            (const float4*)(qkv + ((size_t)(b * N) + toks[i]) * C3 + head * D);
        ((float4*)ks)[idx] = base[C / 4 + p];        // k (+256 floats)
        ((float4*)vs)[idx] = base[2 * (C / 4) + p];  // v (+512 floats)
    }
    __syncthreads();

    float ls    = logit_scale[0];
    float scale = __expf(fminf(ls, 4.6051701859880914f));   // log(100)

    float m = -INFINITY, sum = 0.f;
    float4 acc[8];
#pragma unroll
    for (int p = 0; p < 8; p++) acc[p] = make_float4(0.f, 0.f, 0.f, 0.f);

    for (int j0 = 0; j0 < GS; j0 += JT) {
        // ---- QK tile: 8 independent dot products ----
        float dots[JT];
#pragma unroll
        for (int jj = 0; jj < JT; jj++) {
            float dx = 0.f, dy = 0.f, dz = 0.f, dw = 0.f;
#pragma unroll
            for (int p = 0; p < 8; p++) {
                float4 k4 = ((float4*)ks)[(j0 + jj) * 8 + p];  // smem broadcast
                dx += qr[p].x * k4.x;
                dy += qr[p].y * k4.y;
                dz += qr[p].z * k4.z;
                dw += qr[p].w * k4.w;
            }
            dots[jj] = ((dx + dy) + (dz + dw)) * scale;
        }

        // ---- online softmax update ----
        float tm = dots[0];
#pragma unroll
        for (int jj = 1; jj < JT; jj++) tm = fmaxf(tm, dots[jj]);
        float m_new = fmaxf(m, tm);
        float c = __expf(m - m_new);     // 0 on first tile (m = -inf)
        sum *= c;
#pragma unroll
        for (int p = 0; p < 8; p++) {
            acc[p].x *= c; acc[p].y *= c; acc[p].z *= c; acc[p].w *= c;
        }
#pragma unroll
        for (int jj = 0; jj < JT; jj++) {
            float pj = __expf(dots[jj] - m_new);
            sum += pj;
#pragma unroll
            for (int p = 0; p < 8; p++) {
                float4 v4 = ((float4*)vs)[(j0 + jj) * 8 + p];  // smem broadcast
                acc[p].x += pj * v4.x;
                acc[p].y += pj * v4.y;
                acc[p].z += pj * v4.z;
                acc[p].w += pj * v4.w;
            }
        }
        m = m_new;
    }

    float rinv = 1.0f / sum;

    // scatter straight back to ORIGINAL token order (fuses inverse permutation)
    float4* outp = (float4*)(g_y + ((size_t)(b * N) + toks[tid]) * C + head * D);
#pragma unroll
    for (int p = 0; p < 8; p++) {
        acc[p].x *= rinv; acc[p].y *= rinv; acc[p].z *= rinv; acc[p].w *= rinv;
        outp[p] = acc[p];
    }
}

// ---------------- K5: projection GEMM  out = y @ W^T + b ----------------
// M = B*N = 65536, N = 256, K = 256. 64x64x16 tiles, 256 threads, 4x4 per thread.
#define BM 64
#define BN 64
#define BK 16
#define PAD 4

__global__ void k_proj(const float* __restrict__ W,
                       const float* __restrict__ bias,
                       float* __restrict__ out) {
    __shared__ float As[BK][BM + PAD];
    __shared__ float Bs[BK][BN + PAD];

    int tid = threadIdx.x;          // 256
    int tx = tid & 15, ty = tid >> 4;
    int m0 = blockIdx.y * BM;
    int n0 = blockIdx.x * BN;

    int lr  = tid >> 2;             // 0..63  (row within tile)
    int lc4 = tid & 3;              // 0..3   (float4 within 16-wide K slab)

    const float* A = g_y;
    float acc[4][4] = {};

    for (int k0 = 0; k0 < C; k0 += BK) {
        float4 a4 = *(const float4*)(A + (size_t)(m0 + lr) * C + k0 + lc4 * 4);
        float4 b4 = *(const float4*)(W + (size_t)(n0 + lr) * C + k0 + lc4 * 4);
        As[lc4 * 4 + 0][lr] = a4.x; As[lc4 * 4 + 1][lr] = a4.y;
        As[lc4 * 4 + 2][lr] = a4.z; As[lc4 * 4 + 3][lr] = a4.w;
        Bs[lc4 * 4 + 0][lr] = b4.x; Bs[lc4 * 4 + 1][lr] = b4.y;
        Bs[lc4 * 4 + 2][lr] = b4.z; Bs[lc4 * 4 + 3][lr] = b4.w;
        __syncthreads();

#pragma unroll
        for (int k = 0; k < BK; k++) {
            float4 av = *(const float4*)&As[k][ty * 4];
            float4 bv = *(const float4*)&Bs[k][tx * 4];
            acc[0][0] += av.x * bv.x; acc[0][1] += av.x * bv.y;
            acc[0][2] += av.x * bv.z; acc[0][3] += av.x * bv.w;
            acc[1][0] += av.y * bv.x; acc[1][1] += av.y * bv.y;
            acc[1][2] += av.y * bv.z; acc[1][3] += av.y * bv.w;
            acc[2][0] += av.z * bv.x; acc[2][1] += av.z * bv.y;
            acc[2][2] += av.z * bv.z; acc[2][3] += av.z * bv.w;
            acc[3][0] += av.w * bv.x; acc[3][1] += av.w * bv.y;
            acc[3][2] += av.w * bv.z; acc[3][3] += av.w * bv.w;
        }
        __syncthreads();
    }

    float4 bv = *(const float4*)(bias + n0 + tx * 4);
#pragma unroll
    for (int i = 0; i < 4; i++) {
        float4 o;
        o.x = acc[i][0] + bv.x;
        o.y = acc[i][1] + bv.y;
        o.z = acc[i][2] + bv.z;
        o.w = acc[i][3] + bv.w;
        *(float4*)(out + (size_t)(m0 + ty * 4 + i) * C + n0 + tx * 4) = o;
    }
}

// ---------------- launch ----------------
extern "C" void kernel_launch(void* const* d_in, const int* in_sizes, int n_in,
                              void* d_out, int out_size) {
    const float* qkv  = (const float*)d_in[0];
    const float* sim  = (const float*)d_in[1];
    const float* W    = (const float*)d_in[2];
    const float* bias = (const float*)d_in[3];
    const float* ls   = (const float*)d_in[4];
    float* out = (float*)d_out;

    k_argmax_count<<<dim3(NCH, B), CHUNK>>>(sim);
    k_scan<<<B, 1024>>>();
    k_scatter<<<dim3(NCH, B), CHUNK>>>();
    k_attn<<<dim3(HDS, NG, B), GS>>>(qkv, ls);
    k_proj<<<dim3(C / BN, (B * N) / BM), 256>>>(W, bias, out);
}

// round 3
// speedup vs baseline: 1.3127x; 1.1347x over previous
#include <cuda_runtime.h>
#include <math.h>

// Problem constants (fixed by the dataset)
#define B    4
#define N    16384
#define C    256
#define C3   768
#define T    64        // categories
#define HDS  8
#define D    32        // head dim
#define GS   128       // group size
#define NG   128       // groups per batch
#define CHUNK 128
#define NCH   128      // N / CHUNK
#define JT   8         // key tile for online softmax

// ---------------- scratch (static device allocations only) ----------------
__device__ int   g_tkid[B * N];
__device__ int   g_counts[B * T * NCH];     // [b][key][chunk], scanned in place
__device__ int   g_sortidx[B * N];          // sorted position -> original token
__device__ float g_y[(size_t)B * N * C];    // attention output in ORIGINAL token order

// ---------------- K1: per-token argmax + per-chunk histogram ----------------
__global__ void k_argmax_count(const float* __restrict__ sim) {
    int b = blockIdx.y, ch = blockIdx.x, tid = threadIdx.x;
    __shared__ float ss[CHUNK * T];   // 32 KB
    __shared__ int   hist[T];

    const float4* src = (const float4*)(sim + ((size_t)(b * N + ch * CHUNK)) * T);
    float4* dst = (float4*)ss;
#pragma unroll
    for (int i = tid; i < CHUNK * T / 4; i += CHUNK) dst[i] = src[i];
    if (tid < T) hist[tid] = 0;
    __syncthreads();

    const float* row = ss + tid * T;
    float best = row[0];
    int   bi   = 0;
#pragma unroll
    for (int j = 1; j < T; j++) {
        float v = row[j];
        if (v > best) { best = v; bi = j; }   // first-max == jnp.argmax tie rule
    }
    g_tkid[b * N + ch * CHUNK + tid] = bi;
    atomicAdd(&hist[bi], 1);
    __syncthreads();
    if (tid < T) g_counts[(b * T + tid) * NCH + ch] = hist[tid];
}

// ---------------- K2: per-batch exclusive scan of counts (8192 ints) ----------------
__global__ void k_scan() {
    const int PER = (T * NCH) / 1024;   // 8
    int b = blockIdx.x, tid = threadIdx.x;
    __shared__ int t1[1024], t2[1024];
    int* cnt = g_counts + b * T * NCH;

    int v[PER];
    int s = 0;
#pragma unroll
    for (int i = 0; i < PER; i++) { v[i] = cnt[tid * PER + i]; s += v[i]; }
    t1[tid] = s;
    __syncthreads();

    int* a  = t1;
    int* bb = t2;
    for (int off = 1; off < 1024; off <<= 1) {
        int x = a[tid];
        if (tid >= off) x += a[tid - off];
        bb[tid] = x;
        __syncthreads();
        int* tmp = a; a = bb; bb = tmp;
    }
    int pre = (tid == 0) ? 0 : a[tid - 1];
#pragma unroll
    for (int i = 0; i < PER; i++) { cnt[tid * PER + i] = pre; pre += v[i]; }
}

// ---------------- K3: stable scatter (counting-sort placement) ----------------
__global__ void k_scatter() {
    int b = blockIdx.y, ch = blockIdx.x, tid = threadIdx.x;
    __shared__ int keys[CHUNK];
    int token = ch * CHUNK + tid;
    int key   = g_tkid[b * N + token];
    keys[tid] = key;
    __syncthreads();
    int rank = 0;
    for (int j = 0; j < tid; j++) rank += (keys[j] == key);
    int pos = g_counts[(b * T + key) * NCH + ch] + rank;
    g_sortidx[b * N + pos] = token;
}

// ---------------- K4: grouped attention (flash-style, 2 query rows/thread) ----
// One block of 64 threads per (head, group, batch); thread owns rows tid, tid+64.
// Each k4/v4 smem broadcast load now feeds 8 FMAs instead of 4.
__global__ void __launch_bounds__(64, 5)
k_attn(const float* __restrict__ qkv, const float* __restrict__ logit_scale) {
    __shared__ float ks[GS * D];
    __shared__ float vs[GS * D];
    __shared__ int   toks[GS];

    int head = blockIdx.x, g = blockIdx.y, b = blockIdx.z;
    int tid = threadIdx.x;

    toks[tid]      = g_sortidx[b * N + g * GS + tid];
    toks[tid + 64] = g_sortidx[b * N + g * GS + tid + 64];
    __syncthreads();

    // q rows straight to registers
    const float4* qb0 =
        (const float4*)(qkv + ((size_t)(b * N) + toks[tid]) * C3 + head * D);
    const float4* qb1 =
        (const float4*)(qkv + ((size_t)(b * N) + toks[tid + 64]) * C3 + head * D);
    float4 q0[8], q1[8];
#pragma unroll
    for (int p = 0; p < 8; p++) { q0[p] = qb0[p]; q1[p] = qb1[p]; }

    // cooperative gather of k and v into smem (1024 float4 each, 64 threads)
    for (int idx = tid; idx < GS * (D / 4); idx += 64) {
        int i = idx >> 3, p = idx & 7;
        const float4* base =
            (const float4*)(qkv + ((size_t)(b * N) + toks[i]) * C3 + head * D);
        ((float4*)ks)[idx] = base[C / 4 + p];        // k (+256 floats)
        ((float4*)vs)[idx] = base[2 * (C / 4) + p];  // v (+512 floats)
    }
    __syncthreads();

    float ls    = logit_scale[0];
    float scale = __expf(fminf(ls, 4.6051701859880914f));   // log(100)

    float  m0v = -INFINITY, s0 = 0.f;
    float  m1v = -INFINITY, s1 = 0.f;
    float4 a0[8], a1[8];
#pragma unroll
    for (int p = 0; p < 8; p++) {
        a0[p] = make_float4(0.f, 0.f, 0.f, 0.f);
        a1[p] = make_float4(0.f, 0.f, 0.f, 0.f);
    }

    for (int j0 = 0; j0 < GS; j0 += JT) {
        float d0[JT], d1[JT];
#pragma unroll
        for (int jj = 0; jj < JT; jj++) {
            float x0 = 0.f, y0 = 0.f, x1 = 0.f, y1 = 0.f;
#pragma unroll
            for (int p = 0; p < 8; p++) {
                float4 k4 = ((float4*)ks)[(j0 + jj) * 8 + p];  // broadcast
                x0 += q0[p].x * k4.x; y0 += q0[p].y * k4.y;
                x0 += q0[p].z * k4.z; y0 += q0[p].w * k4.w;
                x1 += q1[p].x * k4.x; y1 += q1[p].y * k4.y;
                x1 += q1[p].z * k4.z; y1 += q1[p].w * k4.w;
            }
            d0[jj] = (x0 + y0) * scale;
            d1[jj] = (x1 + y1) * scale;
        }

        // online softmax update (both rows)
        float t0 = d0[0], t1 = d1[0];
#pragma unroll
        for (int jj = 1; jj < JT; jj++) {
            t0 = fmaxf(t0, d0[jj]);
            t1 = fmaxf(t1, d1[jj]);
        }
        float n0 = fmaxf(m0v, t0), n1 = fmaxf(m1v, t1);
        float c0 = __expf(m0v - n0), c1 = __expf(m1v - n1);
        s0 *= c0; s1 *= c1;
#pragma unroll
        for (int p = 0; p < 8; p++) {
            a0[p].x *= c0; a0[p].y *= c0; a0[p].z *= c0; a0[p].w *= c0;
            a1[p].x *= c1; a1[p].y *= c1; a1[p].z *= c1; a1[p].w *= c1;
        }
#pragma unroll
        for (int jj = 0; jj < JT; jj++) {
            float p0 = __expf(d0[jj] - n0);
            float p1 = __expf(d1[jj] - n1);
            s0 += p0; s1 += p1;
#pragma unroll
            for (int p = 0; p < 8; p++) {
                float4 v4 = ((float4*)vs)[(j0 + jj) * 8 + p];  // broadcast
                a0[p].x += p0 * v4.x; a0[p].y += p0 * v4.y;
                a0[p].z += p0 * v4.z; a0[p].w += p0 * v4.w;
                a1[p].x += p1 * v4.x; a1[p].y += p1 * v4.y;
                a1[p].z += p1 * v4.z; a1[p].w += p1 * v4.w;
            }
        }
        m0v = n0; m1v = n1;
    }

    float r0 = 1.0f / s0, r1 = 1.0f / s1;

    // scatter straight back to ORIGINAL token order (fuses inverse permutation)
    float4* o0 = (float4*)(g_y + ((size_t)(b * N) + toks[tid]) * C + head * D);
    float4* o1 = (float4*)(g_y + ((size_t)(b * N) + toks[tid + 64]) * C + head * D);
#pragma unroll
    for (int p = 0; p < 8; p++) {
        a0[p].x *= r0; a0[p].y *= r0; a0[p].z *= r0; a0[p].w *= r0;
        o0[p] = a0[p];
        a1[p].x *= r1; a1[p].y *= r1; a1[p].z *= r1; a1[p].w *= r1;
        o1[p] = a1[p];
    }
}

// ---------------- K5: projection GEMM  out = y @ W^T + b ----------------
// M = 65536, N = 256, K = 256. 128x128x8 tiles, 256 threads, 8x8 per thread.
#define PBM 128
#define PBN 128
#define PBK 8
#define PPAD 4

__global__ void __launch_bounds__(256)
k_proj(const float* __restrict__ W, const float* __restrict__ bias,
       float* __restrict__ out) {
    __shared__ float As[PBK][PBM + PPAD];
    __shared__ float Bs[PBK][PBN + PPAD];

    int tid = threadIdx.x;          // 256
    int m0 = blockIdx.y * PBM;
    int n0 = blockIdx.x * PBN;

    int lr = tid >> 1;              // 0..127 (row within tile)
    int lk = (tid & 1) * 4;         // 0 or 4 (float4 within 8-wide K slab)
    int tx = tid & 15, ty = tid >> 4;   // 16 x 16 thread grid, 8x8 frags

    const float* A = g_y;
    float acc[8][8] = {};

    for (int k0 = 0; k0 < C; k0 += PBK) {
        float4 a4 = *(const float4*)(A + (size_t)(m0 + lr) * C + k0 + lk);
        float4 b4 = *(const float4*)(W + (size_t)(n0 + lr) * C + k0 + lk);
        As[lk + 0][lr] = a4.x; As[lk + 1][lr] = a4.y;
        As[lk + 2][lr] = a4.z; As[lk + 3][lr] = a4.w;
        Bs[lk + 0][lr] = b4.x; Bs[lk + 1][lr] = b4.y;
        Bs[lk + 2][lr] = b4.z; Bs[lk + 3][lr] = b4.w;
        __syncthreads();

#pragma unroll
        for (int k = 0; k < PBK; k++) {
            float av[8], bv[8];
            *(float4*)&av[0] = *(const float4*)&As[k][ty * 8];
            *(float4*)&av[4] = *(const float4*)&As[k][ty * 8 + 4];
            *(float4*)&bv[0] = *(const float4*)&Bs[k][tx * 8];
            *(float4*)&bv[4] = *(const float4*)&Bs[k][tx * 8 + 4];
#pragma unroll
            for (int i = 0; i < 8; i++)
#pragma unroll
                for (int j = 0; j < 8; j++)
                    acc[i][j] += av[i] * bv[j];
        }
        __syncthreads();
    }

#pragma unroll
    for (int i = 0; i < 8; i++) {
        float4 o0, o1;
        const float* bb = bias + n0 + tx * 8;
        o0.x = acc[i][0] + bb[0]; o0.y = acc[i][1] + bb[1];
        o0.z = acc[i][2] + bb[2]; o0.w = acc[i][3] + bb[3];
        o1.x = acc[i][4] + bb[4]; o1.y = acc[i][5] + bb[5];
        o1.z = acc[i][6] + bb[6]; o1.w = acc[i][7] + bb[7];
        float* op = out + (size_t)(m0 + ty * 8 + i) * C + n0 + tx * 8;
        *(float4*)op       = o0;
        *(float4*)(op + 4) = o1;
    }
}

// ---------------- launch ----------------
extern "C" void kernel_launch(void* const* d_in, const int* in_sizes, int n_in,
                              void* d_out, int out_size) {
    const float* qkv  = (const float*)d_in[0];
    const float* sim  = (const float*)d_in[1];
    const float* W    = (const float*)d_in[2];
    const float* bias = (const float*)d_in[3];
    const float* ls   = (const float*)d_in[4];
    float* out = (float*)d_out;

    k_argmax_count<<<dim3(NCH, B), CHUNK>>>(sim);
    k_scan<<<B, 1024>>>();
    k_scatter<<<dim3(NCH, B), CHUNK>>>();
    k_attn<<<dim3(HDS, NG, B), 64>>>(qkv, ls);
    k_proj<<<dim3(C / PBN, (B * N) / PBM), 256>>>(W, bias, out);
}

// round 5
// speedup vs baseline: 1.6885x; 1.2863x over previous
#include <cuda_runtime.h>
#include <cuda_bf16.h>
#include <math.h>
#include <cstdint>

// Problem constants (fixed by the dataset)
#define B    4
#define N    16384
#define C    256
#define C3   768
#define T    64        // categories
#define HDS  8
#define D    32        // head dim
#define GS   128       // group size
#define NG   128       // groups per batch
#define CHUNK 128
#define NCH   128      // N / CHUNK
#define JT   8         // key tile for online softmax

// ---------------- scratch (static device allocations only) ----------------
__device__ int   g_tkid[B * N];
__device__ int   g_counts[B * T * NCH];     // [b][key][chunk], scanned in place
__device__ int   g_sortidx[B * N];          // sorted position -> original token
__device__ float g_y[(size_t)B * N * C];    // attention output in ORIGINAL token order

// bf16 hi/lo split of a pair of floats, packed as bf16x2 words
__device__ __forceinline__ void split2(float a, float b, uint32_t& hi, uint32_t& lo) {
    __nv_bfloat162 h = __floats2bfloat162_rn(a, b);
    float ra = a - __bfloat162float(h.x);
    float rb = b - __bfloat162float(h.y);
    __nv_bfloat162 l = __floats2bfloat162_rn(ra, rb);
    hi = *(uint32_t*)&h;
    lo = *(uint32_t*)&l;
}

// warp-level bf16 MMA, fp32 accumulate (sm_80+, no arch-feature gate)
__device__ __forceinline__ void mma16816(float* c, const uint32_t* a, const uint32_t* b) {
    asm volatile(
        "mma.sync.aligned.m16n8k16.row.col.f32.bf16.bf16.f32 "
        "{%0,%1,%2,%3}, {%4,%5,%6,%7}, {%8,%9}, {%0,%1,%2,%3};"
        : "+f"(c[0]), "+f"(c[1]), "+f"(c[2]), "+f"(c[3])
        : "r"(a[0]), "r"(a[1]), "r"(a[2]), "r"(a[3]), "r"(b[0]), "r"(b[1]));
}

// ---------------- K1: per-token argmax + per-chunk histogram ----------------
__global__ void k_argmax_count(const float* __restrict__ sim) {
    int b = blockIdx.y, ch = blockIdx.x, tid = threadIdx.x;
    __shared__ float ss[CHUNK * T];   // 32 KB
    __shared__ int   hist[T];

    const float4* src = (const float4*)(sim + ((size_t)(b * N + ch * CHUNK)) * T);
    float4* dst = (float4*)ss;
#pragma unroll
    for (int i = tid; i < CHUNK * T / 4; i += CHUNK) dst[i] = src[i];
    if (tid < T) hist[tid] = 0;
    __syncthreads();

    const float* row = ss + tid * T;
    float best = row[0];
    int   bi   = 0;
#pragma unroll
    for (int j = 1; j < T; j++) {
        float v = row[j];
        if (v > best) { best = v; bi = j; }   // first-max == jnp.argmax tie rule
    }
    g_tkid[b * N + ch * CHUNK + tid] = bi;
    atomicAdd(&hist[bi], 1);
    __syncthreads();
    if (tid < T) g_counts[(b * T + tid) * NCH + ch] = hist[tid];
}

// ---------------- K2: per-batch exclusive scan of counts (8192 ints) ----------------
__global__ void k_scan() {
    const int PER = (T * NCH) / 1024;   // 8
    int b = blockIdx.x, tid = threadIdx.x;
    __shared__ int t1[1024], t2[1024];
    int* cnt = g_counts + b * T * NCH;

    int v[PER];
    int s = 0;
#pragma unroll
    for (int i = 0; i < PER; i++) { v[i] = cnt[tid * PER + i]; s += v[i]; }
    t1[tid] = s;
    __syncthreads();

    int* a  = t1;
    int* bb = t2;
    for (int off = 1; off < 1024; off <<= 1) {
        int x = a[tid];
        if (tid >= off) x += a[tid - off];
        bb[tid] = x;
        __syncthreads();
        int* tmp = a; a = bb; bb = tmp;
    }
    int pre = (tid == 0) ? 0 : a[tid - 1];
#pragma unroll
    for (int i = 0; i < PER; i++) { cnt[tid * PER + i] = pre; pre += v[i]; }
}

// ---------------- K3: stable scatter (counting-sort placement) ----------------
__global__ void k_scatter() {
    int b = blockIdx.y, ch = blockIdx.x, tid = threadIdx.x;
    __shared__ int keys[CHUNK];
    int token = ch * CHUNK + tid;
    int key   = g_tkid[b * N + token];
    keys[tid] = key;
    __syncthreads();
    int rank = 0;
    for (int j = 0; j < tid; j++) rank += (keys[j] == key);
    int pos = g_counts[(b * T + key) * NCH + ch] + rank;
    g_sortidx[b * N + pos] = token;
}

// ---------------- K4: grouped attention (flash-style, 2 query rows/thread) ----
__global__ void __launch_bounds__(64, 5)
k_attn(const float* __restrict__ qkv, const float* __restrict__ logit_scale) {
    __shared__ float ks[GS * D];
    __shared__ float vs[GS * D];
    __shared__ int   toks[GS];

    int head = blockIdx.x, g = blockIdx.y, b = blockIdx.z;
    int tid = threadIdx.x;

    toks[tid]      = g_sortidx[b * N + g * GS + tid];
    toks[tid + 64] = g_sortidx[b * N + g * GS + tid + 64];
    __syncthreads();

    const float4* qb0 =
        (const float4*)(qkv + ((size_t)(b * N) + toks[tid]) * C3 + head * D);
    const float4* qb1 =
        (const float4*)(qkv + ((size_t)(b * N) + toks[tid + 64]) * C3 + head * D);
    float4 q0[8], q1[8];
#pragma unroll
    for (int p = 0; p < 8; p++) { q0[p] = qb0[p]; q1[p] = qb1[p]; }

    for (int idx = tid; idx < GS * (D / 4); idx += 64) {
        int i = idx >> 3, p = idx & 7;
        const float4* base =
            (const float4*)(qkv + ((size_t)(b * N) + toks[i]) * C3 + head * D);
        ((float4*)ks)[idx] = base[C / 4 + p];
        ((float4*)vs)[idx] = base[2 * (C / 4) + p];
    }
    __syncthreads();

    float ls    = logit_scale[0];
    float scale = __expf(fminf(ls, 4.6051701859880914f));   // log(100)

    float  m0v = -INFINITY, s0 = 0.f;
    float  m1v = -INFINITY, s1 = 0.f;
    float4 a0[8], a1[8];
#pragma unroll
    for (int p = 0; p < 8; p++) {
        a0[p] = make_float4(0.f, 0.f, 0.f, 0.f);
        a1[p] = make_float4(0.f, 0.f, 0.f, 0.f);
    }

    for (int j0 = 0; j0 < GS; j0 += JT) {
        float d0[JT], d1[JT];
#pragma unroll
        for (int jj = 0; jj < JT; jj++) {
            float x0 = 0.f, y0 = 0.f, x1 = 0.f, y1 = 0.f;
#pragma unroll
            for (int p = 0; p < 8; p++) {
                float4 k4 = ((float4*)ks)[(j0 + jj) * 8 + p];
                x0 += q0[p].x * k4.x; y0 += q0[p].y * k4.y;
                x0 += q0[p].z * k4.z; y0 += q0[p].w * k4.w;
                x1 += q1[p].x * k4.x; y1 += q1[p].y * k4.y;
                x1 += q1[p].z * k4.z; y1 += q1[p].w * k4.w;
            }
            d0[jj] = (x0 + y0) * scale;
            d1[jj] = (x1 + y1) * scale;
        }

        float t0 = d0[0], t1 = d1[0];
#pragma unroll
        for (int jj = 1; jj < JT; jj++) {
            t0 = fmaxf(t0, d0[jj]);
            t1 = fmaxf(t1, d1[jj]);
        }
        float n0 = fmaxf(m0v, t0), n1 = fmaxf(m1v, t1);
        float c0 = __expf(m0v - n0), c1 = __expf(m1v - n1);
        s0 *= c0; s1 *= c1;
#pragma unroll
        for (int p = 0; p < 8; p++) {
            a0[p].x *= c0; a0[p].y *= c0; a0[p].z *= c0; a0[p].w *= c0;
            a1[p].x *= c1; a1[p].y *= c1; a1[p].z *= c1; a1[p].w *= c1;
        }
#pragma unroll
        for (int jj = 0; jj < JT; jj++) {
            float p0 = __expf(d0[jj] - n0);
            float p1 = __expf(d1[jj] - n1);
            s0 += p0; s1 += p1;
#pragma unroll
            for (int p = 0; p < 8; p++) {
                float4 v4 = ((float4*)vs)[(j0 + jj) * 8 + p];
                a0[p].x += p0 * v4.x; a0[p].y += p0 * v4.y;
                a0[p].z += p0 * v4.z; a0[p].w += p0 * v4.w;
                a1[p].x += p1 * v4.x; a1[p].y += p1 * v4.y;
                a1[p].z += p1 * v4.z; a1[p].w += p1 * v4.w;
            }
        }
        m0v = n0; m1v = n1;
    }

    float r0 = 1.0f / s0, r1 = 1.0f / s1;

    float4* o0 = (float4*)(g_y + ((size_t)(b * N) + toks[tid]) * C + head * D);
    float4* o1 = (float4*)(g_y + ((size_t)(b * N) + toks[tid + 64]) * C + head * D);
#pragma unroll
    for (int p = 0; p < 8; p++) {
        a0[p].x *= r0; a0[p].y *= r0; a0[p].z *= r0; a0[p].w *= r0;
        o0[p] = a0[p];
        a1[p].x *= r1; a1[p].y *= r1; a1[p].z *= r1; a1[p].w *= r1;
        o1[p] = a1[p];
    }
}

// ---------------- K5: projection GEMM via warp MMA (bf16 3-term split) -------
// out[m,n] = sum_k y[m,k] * W[n,k] + bias[n]
// Block tile 128(M) x 64(N), 256 threads = 8 warps (4 M x 2 N), warp tile 32x32.
// K chunked at 64. Smem rows padded to 72 bf16 (144 B): frag LDS addresses are
// (36*g + t) words == 4g+t mod 32 -> conflict-free.
#define PM 128
#define PN 64
#define PKC 64
#define PSTR 72                 // bf16 elements per smem row (144 B)
#define SA_HI 0
#define SA_LO (PM * PSTR * 2)
#define SB_HI (SA_LO + PM * PSTR * 2)
#define SB_LO (SB_HI + PN * PSTR * 2)
#define SM_PROJ (SB_LO + PN * PSTR * 2)   // 55296 B

__global__ void __launch_bounds__(256)
k_proj_mma(const float* __restrict__ W, const float* __restrict__ bias,
           float* __restrict__ out) {
    extern __shared__ char sm[];
    int tid = threadIdx.x;
    int wid = tid >> 5, lane = tid & 31;
    int g = lane >> 2, t = lane & 3;
    int wm = wid >> 1, wn = wid & 1;          // 4 x 2 warp grid
    int m0 = blockIdx.y * PM, n0 = blockIdx.x * PN;

    const uint32_t* Ah = (const uint32_t*)(sm + SA_HI);
    const uint32_t* Al = (const uint32_t*)(sm + SA_LO);
    const uint32_t* Bh = (const uint32_t*)(sm + SB_HI);
    const uint32_t* Bl = (const uint32_t*)(sm + SB_LO);
    const int RS = PSTR / 2;                  // 36 words per row

    float acc[2][4][4];
#pragma unroll
    for (int mi = 0; mi < 2; mi++)
#pragma unroll
        for (int ni = 0; ni < 4; ni++)
#pragma unroll
            for (int r = 0; r < 4; r++) acc[mi][ni][r] = 0.f;

    for (int ch = 0; ch < C / PKC; ch++) {
        // ---- fill smem: load fp32, split to bf16 hi/lo ----
#pragma unroll 2
        for (int i = tid; i < PM * (PKC / 4); i += 256) {   // 2048 float4s
            int r = i >> 4, c4 = i & 15;
            float4 v = *(const float4*)(g_y + (size_t)(m0 + r) * C + ch * PKC + c4 * 4);
            uint32_t h0, l0, h1, l1;
            split2(v.x, v.y, h0, l0);
            split2(v.z, v.w, h1, l1);
            int off = r * (PSTR * 2) + c4 * 8;
            *(uint2*)(sm + SA_HI + off) = make_uint2(h0, h1);
            *(uint2*)(sm + SA_LO + off) = make_uint2(l0, l1);
        }
#pragma unroll 2
        for (int i = tid; i < PN * (PKC / 4); i += 256) {   // 1024 float4s
            int r = i >> 4, c4 = i & 15;
            float4 v = *(const float4*)(W + (size_t)(n0 + r) * C + ch * PKC + c4 * 4);
            uint32_t h0, l0, h1, l1;
            split2(v.x, v.y, h0, l0);
            split2(v.z, v.w, h1, l1);
            int off = r * (PSTR * 2) + c4 * 8;
            *(uint2*)(sm + SB_HI + off) = make_uint2(h0, h1);
            *(uint2*)(sm + SB_LO + off) = make_uint2(l0, l1);
        }
        __syncthreads();

        // ---- MMA over 4 k-steps of 16 ----
#pragma unroll
        for (int ksi = 0; ksi < PKC / 16; ksi++) {
            int kw = ksi * 8 + t;   // word offset within row for this lane

            uint32_t ah[2][4], al[2][4];
#pragma unroll
            for (int mi = 0; mi < 2; mi++) {
                int rb = (wm * 32 + mi * 16 + g) * RS + kw;
                ah[mi][0] = Ah[rb];              al[mi][0] = Al[rb];
                ah[mi][1] = Ah[rb + 8 * RS];     al[mi][1] = Al[rb + 8 * RS];
                ah[mi][2] = Ah[rb + 4];          al[mi][2] = Al[rb + 4];
                ah[mi][3] = Ah[rb + 8 * RS + 4]; al[mi][3] = Al[rb + 8 * RS + 4];
            }
            uint32_t bh[4][2], bl[4][2];
#pragma unroll
            for (int ni = 0; ni < 4; ni++) {
                int rb = (wn * 32 + ni * 8 + g) * RS + kw;
                bh[ni][0] = Bh[rb];     bl[ni][0] = Bl[rb];
                bh[ni][1] = Bh[rb + 4]; bl[ni][1] = Bl[rb + 4];
            }
#pragma unroll
            for (int mi = 0; mi < 2; mi++)
#pragma unroll
                for (int ni = 0; ni < 4; ni++) {
                    mma16816(acc[mi][ni], ah[mi], bh[ni]);   // hh
                    mma16816(acc[mi][ni], ah[mi], bl[ni]);   // hl
                    mma16816(acc[mi][ni], al[mi], bh[ni]);   // lh
                }
        }
        __syncthreads();
    }

    // ---- epilogue: bias + store (c0,c1 row g; c2,c3 row g+8; cols 2t,2t+1) ----
#pragma unroll
    for (int ni = 0; ni < 4; ni++) {
        int cn = n0 + wn * 32 + ni * 8 + t * 2;
        float2 bb = *(const float2*)(bias + cn);
#pragma unroll
        for (int mi = 0; mi < 2; mi++) {
            int r0 = m0 + wm * 32 + mi * 16 + g;
            float2 o0, o1;
            o0.x = acc[mi][ni][0] + bb.x;
            o0.y = acc[mi][ni][1] + bb.y;
            o1.x = acc[mi][ni][2] + bb.x;
            o1.y = acc[mi][ni][3] + bb.y;
            *(float2*)(out + (size_t)r0 * C + cn)       = o0;
            *(float2*)(out + (size_t)(r0 + 8) * C + cn) = o1;
        }
    }
}

// ---------------- launch ----------------
extern "C" void kernel_launch(void* const* d_in, const int* in_sizes, int n_in,
                              void* d_out, int out_size) {
    const float* qkv  = (const float*)d_in[0];
    const float* sim  = (const float*)d_in[1];
    const float* W    = (const float*)d_in[2];
    const float* bias = (const float*)d_in[3];
    const float* ls   = (const float*)d_in[4];
    float* out = (float*)d_out;

    cudaFuncSetAttribute(k_proj_mma, cudaFuncAttributeMaxDynamicSharedMemorySize,
                         SM_PROJ);

    k_argmax_count<<<dim3(NCH, B), CHUNK>>>(sim);
    k_scan<<<B, 1024>>>();
    k_scatter<<<dim3(NCH, B), CHUNK>>>();
    k_attn<<<dim3(HDS, NG, B), 64>>>(qkv, ls);
    k_proj_mma<<<dim3(C / PN, (B * N) / PM), 256, SM_PROJ>>>(W, bias, out);
}